// round 2
// baseline (speedup 1.0000x reference)
#include <cuda_runtime.h>
#include <stdint.h>

// fftshift followed by ifftshift on even-sized dims (320, 320):
// net roll = -160 + -160 = -320 ≡ 0 per dim → identity. Output == input.
// This is a pure 104.86 MB copy; the only goal is HBM roofline.

__global__ void copy_f4_kernel(const float4* __restrict__ src,
                               float4* __restrict__ dst,
                               int n4) {
    int i = blockIdx.x * blockDim.x + threadIdx.x;
    if (i < n4) {
        dst[i] = src[i];
    }
}

extern "C" void kernel_launch(void* const* d_in, const int* in_sizes, int n_in,
                              void* d_out, int out_size) {
    const float4* src = (const float4*)d_in[0];
    float4* dst = (float4*)d_out;

    // out_size elements of float32; total bytes are a multiple of 16
    // (8*16*320*320*2 floats = 26,214,400 → 6,553,600 float4s).
    int n4 = out_size / 4;

    const int threads = 256;
    int blocks = (n4 + threads - 1) / threads;
    copy_f4_kernel<<<blocks, threads>>>(src, dst, n4);
}

// round 6
// speedup vs baseline: 1.0172x; 1.0172x over previous
#include <cuda_runtime.h>
#include <stdint.h>

// fftshift ∘ ifftshift on even dims (320,320): net roll ≡ 0 → identity copy.
// Pure 104.86 MB D2D stream; goal is HBM roofline (~7 TB/s → ~24 µs).
//
// MLP=4 per thread: 4 independent stride-batched LDG.128 front-loaded into
// registers, then 4 STG.128. .cs (evict-first) on both sides since the
// 210 MB footprint has zero reuse and exceeds the 126 MB L2.

__global__ void copy_f4x4_kernel(const float4* __restrict__ src,
                                 float4* __restrict__ dst,
                                 int n4) {
    const int stride = gridDim.x * blockDim.x;
    int i = blockIdx.x * blockDim.x + threadIdx.x;

    // Batched main loop: 4 independent loads, then 4 stores.
    for (; i + 3 * stride < n4; i += 4 * stride) {
        float4 a = __ldcs(src + i);
        float4 b = __ldcs(src + i + stride);
        float4 c = __ldcs(src + i + 2 * stride);
        float4 d = __ldcs(src + i + 3 * stride);
        __stcs(dst + i,              a);
        __stcs(dst + i + stride,     b);
        __stcs(dst + i + 2 * stride, c);
        __stcs(dst + i + 3 * stride, d);
    }
    // Tail (empty for the exact-cover launch below, kept for safety).
    for (; i < n4; i += stride) {
        __stcs(dst + i, __ldcs(src + i));
    }
}

extern "C" void kernel_launch(void* const* d_in, const int* in_sizes, int n_in,
                              void* d_out, int out_size) {
    const float4* src = (const float4*)d_in[0];
    float4* dst = (float4*)d_out;

    int n4 = out_size / 4;  // 6,553,600 for this problem

    const int threads = 256;
    // Exact cover: blocks*threads*4 == n4 when n4 divisible; else round up.
    int blocks = (n4 + threads * 4 - 1) / (threads * 4);  // 6400
    copy_f4x4_kernel<<<blocks, threads>>>(src, dst, n4);
}